// round 16
// baseline (speedup 1.0000x reference)
#include <cuda_runtime.h>
#include <math.h>

#define BB 32
#define SS 128
#define NC 128
#define DD 64
#define II 256
#define OD 8192   // NC*DD
#define TOFF (BB*NC*DD)
#define GRID 128
#define NTHR 512

__device__ float g_PE1[NC * DD];
__device__ float g_PE2[SS * OD];        // 4 MB
__device__ float g_P  [BB * SS * DD];
__device__ float g_Su [BB * SS];
__device__ float g_q  [BB];
__device__ float g_C  [BB * NC * SS];
__device__ float g_T  [2 * BB * NC * DD];
__device__ float g_V  [BB * NC * DD];
__device__ float g_Bl [BB * NC * SS];

__device__ unsigned g_cnt = 0;
__device__ unsigned g_gen = 0;

// ---------------------------------------------------------------------------
// Global barrier: 128 co-resident CTAs (1/SM guaranteed: grid<=SMs, 47KB smem).
// ---------------------------------------------------------------------------
__device__ __forceinline__ void gbar() {
    __syncthreads();
    if (threadIdx.x == 0) {
        unsigned gen = *(volatile unsigned*)&g_gen;
        __threadfence();                       // release prior writes
        if (atomicAdd(&g_cnt, 1u) == GRID - 1u) {
            atomicExch(&g_cnt, 0u);
            __threadfence();
            atomicExch(&g_gen, gen + 1u);      // release barrier
        } else {
            while (*(volatile unsigned*)&g_gen == gen) {}
            __threadfence();                   // acquire
        }
    }
    __syncthreads();
}

// ---------------------------------------------------------------------------
// Phase: init. Jobs 0..7 PE2 (512 k each), 8..15 PE1, 16..143 gemmP (32 rows).
// ---------------------------------------------------------------------------
__device__ void p_init(char* sm, const float* __restrict__ u,
                       const float* __restrict__ W) {
    const float LN1E4 = 9.210340371976184f;
    float (*shU)[II] = (float(*)[II])sm;        // 32 x 256 = 32 KB
    for (int job = blockIdx.x; job < 144; job += GRID) {
        if (job < 8) {
            int k = job * 512 + threadIdx.x;     // 0..4095
            float th = expf(-(float)k * (LN1E4 / 4096.0f));
            float sv, cv;
            sincosf(th, &sv, &cv);
            float sc = 0.f, cc = 1.f;
            float2* dst = (float2*)g_PE2;
            #pragma unroll 4
            for (int s = 0; s < SS; s++) {
                dst[s * (OD / 2) + k] = make_float2(sc, cc);
                float ns = sc * cv + cc * sv;
                float nc = cc * cv - sc * sv;
                sc = ns; cc = nc;
            }
            continue;
        }
        if (job < 16) {
            int idx = (job - 8) * 512 + threadIdx.x;   // 0..4095
            int n = idx >> 5, kk = idx & 31;
            float th = expf(-(float)kk * (LN1E4 / 32.0f));
            float sv, cv;
            sincosf((float)n * th, &sv, &cv);
            *(float2*)&g_PE1[n * DD + 2 * kk] = make_float2(sv, cv);
            continue;
        }
        int row0 = (job - 16) * 32;
        __syncthreads();
        for (int idx = threadIdx.x; idx < 32 * 64; idx += NTHR) {
            int r = idx >> 6, i = idx & 63;
            *(float4*)&shU[r][i * 4] = *(const float4*)&u[(row0 + r) * II + i * 4];
        }
        __syncthreads();
        int d = threadIdx.x & 63, g = threadIdx.x >> 6;   // g 0..7
        const float4* u0 = (const float4*)&shU[g][0];
        const float4* u1 = (const float4*)&shU[g + 8][0];
        const float4* u2 = (const float4*)&shU[g + 16][0];
        const float4* u3 = (const float4*)&shU[g + 24][0];
        float a0 = 0, a1 = 0, a2 = 0, a3 = 0;
        #pragma unroll 8
        for (int i4 = 0; i4 < II / 4; i4++) {
            float4 f0 = u0[i4], f1 = u1[i4], f2 = u2[i4], f3 = u3[i4];
            float w0 = __ldg(&W[(i4 * 4 + 0) * DD + d]);
            float w1 = __ldg(&W[(i4 * 4 + 1) * DD + d]);
            float w2 = __ldg(&W[(i4 * 4 + 2) * DD + d]);
            float w3 = __ldg(&W[(i4 * 4 + 3) * DD + d]);
            a0 += f0.x * w0 + f0.y * w1 + f0.z * w2 + f0.w * w3;
            a1 += f1.x * w0 + f1.y * w1 + f1.z * w2 + f1.w * w3;
            a2 += f2.x * w0 + f2.y * w1 + f2.z * w2 + f2.w * w3;
            a3 += f3.x * w0 + f3.y * w1 + f3.z * w2 + f3.w * w3;
        }
        g_P[(row0 + g) * DD + d]      = a0;
        g_P[(row0 + g + 8) * DD + d]  = a1;
        g_P[(row0 + g + 16) * DD + d] = a2;
        g_P[(row0 + g + 24) * DD + d] = a3;
        int r = threadIdx.x >> 4, t = threadIdx.x & 15;   // r 0..31
        float sm2 = 0.f;
        for (int i = t; i < II; i += 16) sm2 += shU[r][i];
        sm2 += __shfl_xor_sync(0xffffffffu, sm2, 8);
        sm2 += __shfl_xor_sync(0xffffffffu, sm2, 4);
        sm2 += __shfl_xor_sync(0xffffffffu, sm2, 2);
        sm2 += __shfl_xor_sync(0xffffffffu, sm2, 1);
        if (t == 0) g_Su[row0 + r] = sm2;
    }
}

// ---------------------------------------------------------------------------
// Phase: A0 (iter-0 shortcut). Jobs 0..31 (one per b).
// ---------------------------------------------------------------------------
__device__ void p_A0(char* sm, const float* __restrict__ mask) {
    float (*shT)[64] = (float(*)[64])sm;    // 8 x 64
    float* shQ = (float*)(sm + 8 * 64 * 4); // 8
    for (int job = blockIdx.x; job < BB; job += GRID) {
        int b = job;
        int d = threadIdx.x & 63, g = threadIdx.x >> 6;  // g 0..7, 16 s each
        const float* Pb = &g_P[b * SS * DD];
        float a = 0.f, q = 0.f;
        for (int j = 0; j < 16; j++) {
            int s = g * 16 + j;
            float c = mask[b * SS + s] * (1.0f / 128.0f);
            a += c * Pb[s * DD + d];
            q += c * g_Su[b * SS + s];
        }
        shT[g][d] = a;
        if (d == 0) shQ[g] = q;
        __syncthreads();
        if (threadIdx.x < 64) {
            float t = 0.f;
            #pragma unroll
            for (int gg = 0; gg < 8; gg++) t += shT[gg][threadIdx.x];
            g_T[b * DD + threadIdx.x] = t;
            if (threadIdx.x == 0) {
                float qq = 0.f;
                #pragma unroll
                for (int gg = 0; gg < 8; gg++) qq += shQ[gg];
                g_q[b] = qq;
            }
        }
        __syncthreads();
    }
}

// ---------------------------------------------------------------------------
// Phase: outA (terms 1+2, s-halves). Jobs 0..127: half, ntile(64n), b.
// ---------------------------------------------------------------------------
__device__ void p_outA(char* sm) {
    float*  shP  = (float*)sm;                         // 64*64 = 16 KB
    float4* shC4 = (float4*)(sm + 16384);              // 64n x 16 = 16 KB
    float4* shSu4 = (float4*)(sm + 32768);             // 16
    for (int job = blockIdx.x; job < 128; job += GRID) {
        int half = job & 1;
        int n0   = ((job >> 1) & 1) * 64;
        int b    = job >> 2;
        int sb   = half * 64;
        for (int idx = threadIdx.x; idx < 64 * 16; idx += NTHR)
            *(float4*)&shP[idx * 4] = *(const float4*)&g_P[(b * SS + sb) * DD + idx * 4];
        for (int idx = threadIdx.x; idx < 64 * 16; idx += NTHR) {
            int nr = idx >> 4, sc = idx & 15;
            shC4[idx] = *(const float4*)&g_C[(b * NC + n0 + nr) * SS + sb + sc * 4];
        }
        if (threadIdx.x < 16)
            shSu4[threadIdx.x] = *(const float4*)&g_Su[b * SS + sb + threadIdx.x * 4];
        __syncthreads();
        int d = threadIdx.x & 63, g = threadIdx.x >> 6;   // g 0..7, 8 n each
        float* T = g_T + half * TOFF;
        #pragma unroll
        for (int nq = 0; nq < 2; nq++) {
            int nb = g * 8 + nq * 4;
            const float4* c0 = &shC4[(nb + 0) * 16];
            const float4* c1 = &shC4[(nb + 1) * 16];
            const float4* c2 = &shC4[(nb + 2) * 16];
            const float4* c3 = &shC4[(nb + 3) * 16];
            float a0 = 0, a1 = 0, a2 = 0, a3 = 0, q0 = 0, q1 = 0, q2 = 0, q3 = 0;
            #pragma unroll
            for (int s4 = 0; s4 < 16; s4++) {
                float4 f0 = c0[s4], f1 = c1[s4], f2 = c2[s4], f3 = c3[s4];
                float4 su = shSu4[s4];
                float p0 = shP[(s4 * 4 + 0) * DD + d];
                float p1 = shP[(s4 * 4 + 1) * DD + d];
                float p2 = shP[(s4 * 4 + 2) * DD + d];
                float p3 = shP[(s4 * 4 + 3) * DD + d];
                a0 += f0.x * p0 + f0.y * p1 + f0.z * p2 + f0.w * p3;
                a1 += f1.x * p0 + f1.y * p1 + f1.z * p2 + f1.w * p3;
                a2 += f2.x * p0 + f2.y * p1 + f2.z * p2 + f2.w * p3;
                a3 += f3.x * p0 + f3.y * p1 + f3.z * p2 + f3.w * p3;
                q0 += f0.x * su.x + f0.y * su.y + f0.z * su.z + f0.w * su.w;
                q1 += f1.x * su.x + f1.y * su.y + f1.z * su.z + f1.w * su.w;
                q2 += f2.x * su.x + f2.y * su.y + f2.z * su.z + f2.w * su.w;
                q3 += f3.x * su.x + f3.y * su.y + f3.z * su.z + f3.w * su.w;
            }
            int n = n0 + nb;
            T[(b * NC + n + 0) * DD + d] = a0 + q0 * g_PE1[(n + 0) * DD + d];
            T[(b * NC + n + 1) * DD + d] = a1 + q1 * g_PE1[(n + 1) * DD + d];
            T[(b * NC + n + 2) * DD + d] = a2 + q2 * g_PE1[(n + 2) * DD + d];
            T[(b * NC + n + 3) * DD + d] = a3 + q3 * g_PE1[(n + 3) * DD + d];
        }
        __syncthreads();
    }
}

// ---------------------------------------------------------------------------
// Phase: outB (term 3 + squash + fused logit term 3). Jobs 0..255: (n, b-half).
// ---------------------------------------------------------------------------
__device__ void p_outB(char* sm, float* __restrict__ dst, int final_, int it0,
                       const float* __restrict__ mask) {
    float*  shPE2 = (float*)sm;                        // 128*68*4 = 34816
    float4* shC4  = (float4*)(sm + 34816);             // 16b x 32 = 8192
    float*  shV   = (float*)(sm + 34816 + 8192);       // 16*64*4 = 4096
    float*  shRed0 = (float*)(sm + 34816 + 8192 + 4096);       // 16
    float*  shRed1 = (float*)(sm + 34816 + 8192 + 4096 + 64);  // 16
    float* Vout = final_ ? dst : g_V;
    for (int job = blockIdx.x; job < 256; job += GRID) {
        int n  = job >> 1;
        int b0 = (job & 1) * 16;
        for (int idx = threadIdx.x; idx < SS * 16; idx += NTHR) {
            int s = idx >> 4, c = idx & 15;
            *(float4*)&shPE2[s * 68 + c * 4] = *(const float4*)&g_PE2[s * OD + n * DD + c * 4];
        }
        {
            int idx = threadIdx.x;              // 512 = 16*32
            int bl = idx >> 5, sc = idx & 31;
            if (it0) {
                float4 m = *(const float4*)&mask[(b0 + bl) * SS + sc * 4];
                shC4[idx] = make_float4(m.x * (1.0f / 128.0f), m.y * (1.0f / 128.0f),
                                        m.z * (1.0f / 128.0f), m.w * (1.0f / 128.0f));
            } else {
                shC4[idx] = *(const float4*)&g_C[((b0 + bl) * NC + n) * SS + sc * 4];
            }
        }
        __syncthreads();
        int d = threadIdx.x & 63, g = threadIdx.x >> 6;
        int lane = threadIdx.x & 31, wig = (threadIdx.x >> 5) & 1;
        const float4* c0 = &shC4[(g * 2 + 0) * 32];
        const float4* c1 = &shC4[(g * 2 + 1) * 32];
        float a0 = 0, a1 = 0;
        #pragma unroll
        for (int s4 = 0; s4 < 32; s4++) {
            float4 f0 = c0[s4], f1 = c1[s4];
            float p0 = shPE2[(s4 * 4 + 0) * 68 + d];
            float p1 = shPE2[(s4 * 4 + 1) * 68 + d];
            float p2 = shPE2[(s4 * 4 + 2) * 68 + d];
            float p3 = shPE2[(s4 * 4 + 3) * 68 + d];
            a0 += f0.x * p0 + f0.y * p1 + f0.z * p2 + f0.w * p3;
            a1 += f1.x * p0 + f1.y * p1 + f1.z * p2 + f1.w * p3;
        }
        int bA = b0 + g * 2, bBd = bA + 1;
        float val0, val1;
        if (it0) {
            float pe = g_PE1[n * DD + d];
            val0 = g_T[bA  * DD + d] + g_q[bA]  * pe + a0;
            val1 = g_T[bBd * DD + d] + g_q[bBd] * pe + a1;
        } else {
            val0 = g_T[(bA * NC + n) * DD + d] + g_T[TOFF + (bA * NC + n) * DD + d] + a0;
            val1 = g_T[(bBd * NC + n) * DD + d] + g_T[TOFF + (bBd * NC + n) * DD + d] + a1;
        }
        float ss0 = val0 * val0, ss1 = val1 * val1;
        #pragma unroll
        for (int off = 16; off; off >>= 1) {
            ss0 += __shfl_xor_sync(0xffffffffu, ss0, off);
            ss1 += __shfl_xor_sync(0xffffffffu, ss1, off);
        }
        if (lane == 0) { shRed0[g * 2 + wig] = ss0; shRed1[g * 2 + wig] = ss1; }
        __syncthreads();
        float t0 = shRed0[g * 2] + shRed0[g * 2 + 1];
        float t1 = shRed1[g * 2] + shRed1[g * 2 + 1];
        float sc0 = t0 / (1.0f + t0) * rsqrtf(t0 + 1e-7f);
        float sc1 = t1 / (1.0f + t1) * rsqrtf(t1 + 1e-7f);
        float v0w = sc0 * val0, v1w = sc1 * val1;
        Vout[(bA  * NC + n) * DD + d] = v0w;
        Vout[(bBd * NC + n) * DD + d] = v1w;
        if (!final_) {
            shV[(g * 2 + 0) * DD + d] = v0w;
            shV[(g * 2 + 1) * DD + d] = v1w;
            __syncthreads();
            int s = threadIdx.x & 127, h = threadIdx.x >> 7;
            int bl = h * 4;
            const float4* pr = (const float4*)&shPE2[s * 68];
            const float4* w0 = (const float4*)&shV[(bl + 0) * DD];
            const float4* w1 = (const float4*)&shV[(bl + 1) * DD];
            const float4* w2 = (const float4*)&shV[(bl + 2) * DD];
            const float4* w3 = (const float4*)&shV[(bl + 3) * DD];
            float r0 = 0, r1 = 0, r2 = 0, r3 = 0;
            #pragma unroll
            for (int d4 = 0; d4 < 16; d4++) {
                float4 p = pr[d4];
                float4 x0 = w0[d4], x1 = w1[d4], x2 = w2[d4], x3 = w3[d4];
                r0 += p.x * x0.x + p.y * x0.y + p.z * x0.z + p.w * x0.w;
                r1 += p.x * x1.x + p.y * x1.y + p.z * x1.z + p.w * x1.w;
                r2 += p.x * x2.x + p.y * x2.y + p.z * x2.z + p.w * x2.w;
                r3 += p.x * x3.x + p.y * x3.y + p.z * x3.z + p.w * x3.w;
            }
            g_Bl[((b0 + bl + 0) * NC + n) * SS + s] = r0;
            g_Bl[((b0 + bl + 1) * NC + n) * SS + s] = r1;
            g_Bl[((b0 + bl + 2) * NC + n) * SS + s] = r2;
            g_Bl[((b0 + bl + 3) * NC + n) * SS + s] = r3;
        }
        __syncthreads();
    }
}

// ---------------------------------------------------------------------------
// Phase: bA (logit terms 1+2, += onto term 3). Jobs 0..127: (b, 32n).
// ---------------------------------------------------------------------------
__device__ void p_bA(char* sm) {
    float* shP  = (float*)sm;                          // 128*68*4 = 34816
    float* shV  = (float*)(sm + 34816);                // 32*64*4 = 8192
    float* shSu = (float*)(sm + 34816 + 8192);         // 128
    float* shSc = (float*)(sm + 34816 + 8192 + 512);   // 32
    for (int job = blockIdx.x; job < 128; job += GRID) {
        int b  = job >> 2;
        int n0 = (job & 3) * 32;
        for (int idx = threadIdx.x; idx < SS * 16; idx += NTHR) {
            int s = idx >> 4, c = idx & 15;
            *(float4*)&shP[s * 68 + c * 4] = *(const float4*)&g_P[(b * SS + s) * DD + c * 4];
        }
        {
            int idx = threadIdx.x;              // 512 = 32*16 float4
            *(float4*)&shV[idx * 4] = *(const float4*)&g_V[(b * NC + n0) * DD + idx * 4];
        }
        if (threadIdx.x < SS) shSu[threadIdx.x] = g_Su[b * SS + threadIdx.x];
        __syncthreads();
        {
            int w = threadIdx.x >> 5, lane = threadIdx.x & 31;
            #pragma unroll
            for (int j = 0; j < 2; j++) {
                int nl = w + j * 16;
                float t = shV[nl * DD + lane]      * g_PE1[(n0 + nl) * DD + lane]
                        + shV[nl * DD + 32 + lane] * g_PE1[(n0 + nl) * DD + 32 + lane];
                #pragma unroll
                for (int off = 16; off; off >>= 1)
                    t += __shfl_xor_sync(0xffffffffu, t, off);
                if (lane == 0) shSc[nl] = t;
            }
        }
        __syncthreads();
        int s = threadIdx.x & 127, h = threadIdx.x >> 7;  // h 0..3, 8 n each
        const float4* pr = (const float4*)&shP[s * 68];
        float su = shSu[s];
        #pragma unroll
        for (int nq = 0; nq < 2; nq++) {
            int nl = h * 8 + nq * 4;
            const float4* v0 = (const float4*)&shV[(nl + 0) * DD];
            const float4* v1 = (const float4*)&shV[(nl + 1) * DD];
            const float4* v2 = (const float4*)&shV[(nl + 2) * DD];
            const float4* v3 = (const float4*)&shV[(nl + 3) * DD];
            float a0 = 0, a1 = 0, a2 = 0, a3 = 0;
            #pragma unroll
            for (int d4 = 0; d4 < 16; d4++) {
                float4 p = pr[d4];
                float4 w0 = v0[d4], w1 = v1[d4], w2 = v2[d4], w3 = v3[d4];
                a0 += p.x * w0.x + p.y * w0.y + p.z * w0.z + p.w * w0.w;
                a1 += p.x * w1.x + p.y * w1.y + p.z * w1.z + p.w * w1.w;
                a2 += p.x * w2.x + p.y * w2.y + p.z * w2.z + p.w * w2.w;
                a3 += p.x * w3.x + p.y * w3.y + p.z * w3.z + p.w * w3.w;
            }
            g_Bl[(b * NC + n0 + nl + 0) * SS + s] += a0 + su * shSc[nl + 0];
            g_Bl[(b * NC + n0 + nl + 1) * SS + s] += a1 + su * shSc[nl + 1];
            g_Bl[(b * NC + n0 + nl + 2) * SS + s] += a2 + su * shSc[nl + 2];
            g_Bl[(b * NC + n0 + nl + 3) * SS + s] += a3 + su * shSc[nl + 3];
        }
        __syncthreads();
    }
}

// ---------------------------------------------------------------------------
// Phase: softmax over n -> g_C. Jobs 0..127: (b, 32-s tile). 16 warps x 8 n.
// ---------------------------------------------------------------------------
__device__ void p_softmax(char* sm, const float* __restrict__ mask) {
    float (*red)[16][32] = (float(*)[16][32])sm;   // [2][16][32] = 4 KB
    for (int job = blockIdx.x; job < 128; job += GRID) {
        int b = job >> 2, s0 = (job & 3) * 32;
        int lane = threadIdx.x & 31, w = threadIdx.x >> 5;   // w 0..15
        int s = s0 + lane;
        float v[8];
        float mx = -1e30f;
        #pragma unroll
        for (int j = 0; j < 8; j++) {
            v[j] = g_Bl[(b * NC + w * 8 + j) * SS + s];
            mx = fmaxf(mx, v[j]);
        }
        red[0][w][lane] = mx;
        __syncthreads();
        mx = red[0][0][lane];
        #pragma unroll
        for (int w2 = 1; w2 < 16; w2++) mx = fmaxf(mx, red[0][w2][lane]);
        float sum = 0.f;
        #pragma unroll
        for (int j = 0; j < 8; j++) { v[j] = __expf(v[j] - mx); sum += v[j]; }
        red[1][w][lane] = sum;
        __syncthreads();
        sum = red[1][0][lane];
        #pragma unroll
        for (int w2 = 1; w2 < 16; w2++) sum += red[1][w2][lane];
        float scale = mask[b * SS + s] / sum;
        #pragma unroll
        for (int j = 0; j < 8; j++)
            g_C[(b * NC + w * 8 + j) * SS + s] = v[j] * scale;
        __syncthreads();
    }
}

// ---------------------------------------------------------------------------
// The persistent kernel: all phases, global barriers between.
// ---------------------------------------------------------------------------
__global__ void __launch_bounds__(NTHR) k_all(const float* __restrict__ u,
                                              const float* __restrict__ mask,
                                              const float* __restrict__ W,
                                              float* __restrict__ out) {
    __shared__ __align__(16) char sm[47232];
    p_init(sm, u, W);
    gbar();
    p_A0(sm, mask);
    gbar();
    // iteration 0 (c = mask/128; outA replaced by A0)
    p_outB(sm, out, 0, 1, mask);
    gbar();
    p_bA(sm);
    gbar();
    p_softmax(sm, mask);
    gbar();
    // iteration 1
    p_outA(sm);
    gbar();
    p_outB(sm, out, 0, 0, mask);
    gbar();
    p_bA(sm);
    gbar();
    p_softmax(sm, mask);
    gbar();
    // iteration 2
    p_outA(sm);
    gbar();
    p_outB(sm, out, 1, 0, mask);
}

// ---------------------------------------------------------------------------
extern "C" void kernel_launch(void* const* d_in, const int* in_sizes, int n_in,
                              void* d_out, int out_size) {
    const float* u    = (const float*)d_in[0];
    const float* mask = (const float*)d_in[1];
    const float* W    = (const float*)d_in[2];
    float* out = (float*)d_out;
    k_all<<<GRID, NTHR>>>(u, mask, W, out);
}

// round 17
// speedup vs baseline: 1.2379x; 1.2379x over previous
#include <cuda_runtime.h>
#include <math.h>

#define BB 32
#define SS 128
#define NC 128
#define DD 64
#define II 256
#define OD 8192   // NC*DD
#define TOFF (BB*NC*DD)

__device__ float g_PE1[NC * DD];
__device__ float g_PE2[SS * OD];        // 4 MB
__device__ float g_P  [BB * SS * DD];
__device__ float g_Su [BB * SS];
__device__ float g_q  [BB];
__device__ float g_C  [BB * NC * SS];
__device__ float g_T  [2 * BB * NC * DD];
__device__ float g_V  [BB * NC * DD];
__device__ float g_Bl [BB * NC * SS];

// ---------------------------------------------------------------------------
// Init, 288 blocks: PE2 recurrence / PE1 / gemmP.   (identical to R13)
// ---------------------------------------------------------------------------
__global__ void __launch_bounds__(256) k_init(const float* __restrict__ u,
                                              const float* __restrict__ W) {
    __shared__ float shU[16][II];
    const float LN1E4 = 9.210340371976184f;
    if (blockIdx.x < 16) {
        int k = blockIdx.x * 256 + threadIdx.x;      // 0..4095
        float th = expf(-(float)k * (LN1E4 / 4096.0f));
        float sv, cv;
        sincosf(th, &sv, &cv);
        float sc = 0.f, cc = 1.f;
        float2* dst = (float2*)g_PE2;
        #pragma unroll 4
        for (int s = 0; s < SS; s++) {
            dst[s * (OD / 2) + k] = make_float2(sc, cc);
            float ns = sc * cv + cc * sv;
            float nc = cc * cv - sc * sv;
            sc = ns; cc = nc;
        }
        return;
    }
    if (blockIdx.x < 32) {
        int idx = (blockIdx.x - 16) * 256 + threadIdx.x;
        int n = idx >> 5, kk = idx & 31;
        float th = expf(-(float)kk * (LN1E4 / 32.0f));
        float sv, cv;
        sincosf((float)n * th, &sv, &cv);
        *(float2*)&g_PE1[n * DD + 2 * kk] = make_float2(sv, cv);
        return;
    }
    int row0 = (blockIdx.x - 32) * 16;
    for (int idx = threadIdx.x; idx < 16 * 64; idx += 256) {
        int r = idx >> 6, i = idx & 63;
        *(float4*)&shU[r][i * 4] = *(const float4*)&u[(row0 + r) * II + i * 4];
    }
    __syncthreads();
    int d = threadIdx.x & 63, g = threadIdx.x >> 6;
    const float4* u0 = (const float4*)&shU[g][0];
    const float4* u1 = (const float4*)&shU[g + 4][0];
    const float4* u2 = (const float4*)&shU[g + 8][0];
    const float4* u3 = (const float4*)&shU[g + 12][0];
    float a0 = 0, a1 = 0, a2 = 0, a3 = 0;
    #pragma unroll 8
    for (int i4 = 0; i4 < II / 4; i4++) {
        float4 f0 = u0[i4], f1 = u1[i4], f2 = u2[i4], f3 = u3[i4];
        float w0 = __ldg(&W[(i4 * 4 + 0) * DD + d]);
        float w1 = __ldg(&W[(i4 * 4 + 1) * DD + d]);
        float w2 = __ldg(&W[(i4 * 4 + 2) * DD + d]);
        float w3 = __ldg(&W[(i4 * 4 + 3) * DD + d]);
        a0 += f0.x * w0 + f0.y * w1 + f0.z * w2 + f0.w * w3;
        a1 += f1.x * w0 + f1.y * w1 + f1.z * w2 + f1.w * w3;
        a2 += f2.x * w0 + f2.y * w1 + f2.z * w2 + f2.w * w3;
        a3 += f3.x * w0 + f3.y * w1 + f3.z * w2 + f3.w * w3;
    }
    g_P[(row0 + g) * DD + d]      = a0;
    g_P[(row0 + g + 4) * DD + d]  = a1;
    g_P[(row0 + g + 8) * DD + d]  = a2;
    g_P[(row0 + g + 12) * DD + d] = a3;
    int r = threadIdx.x >> 4, t = threadIdx.x & 15;
    float sm = 0.f;
    for (int i = t; i < II; i += 16) sm += shU[r][i];
    sm += __shfl_xor_sync(0xffffffffu, sm, 8);
    sm += __shfl_xor_sync(0xffffffffu, sm, 4);
    sm += __shfl_xor_sync(0xffffffffu, sm, 2);
    sm += __shfl_xor_sync(0xffffffffu, sm, 1);
    if (t == 0) g_Su[row0 + r] = sm;
}

// ---------------------------------------------------------------------------
// Iter-0 shortcut: T0[b,d], q0[b]. grid = 32.   (identical to R13)
// ---------------------------------------------------------------------------
__global__ void __launch_bounds__(256) k_A0(const float* __restrict__ mask) {
    __shared__ float shT[4][64];
    __shared__ float shQ[4];
    int b = blockIdx.x;
    int d = threadIdx.x & 63, g = threadIdx.x >> 6;
    const float* Pb = &g_P[b * SS * DD];
    float a = 0.f, q = 0.f;
    for (int j = 0; j < 32; j++) {
        int s = g * 32 + j;
        float c = mask[b * SS + s] * (1.0f / 128.0f);
        a += c * Pb[s * DD + d];
        q += c * g_Su[b * SS + s];
    }
    shT[g][d] = a;
    if (d == 0) shQ[g] = q;
    __syncthreads();
    if (threadIdx.x < 64) {
        g_T[b * DD + threadIdx.x] =
            shT[0][threadIdx.x] + shT[1][threadIdx.x] +
            shT[2][threadIdx.x] + shT[3][threadIdx.x];
        if (threadIdx.x == 0) g_q[b] = shQ[0] + shQ[1] + shQ[2] + shQ[3];
    }
}

// ---------------------------------------------------------------------------
// Output terms 1+2, s-split halves. 512 threads; 32 n per block.
// grid = 32 b * 4 ntile * 2 half = 256.   (identical to R13)
// ---------------------------------------------------------------------------
__global__ void __launch_bounds__(512) k_outA() {
    __shared__ float  shP[64 * DD];     // 16 KB
    __shared__ float4 shC4[32 * 16];    // 8 KB
    __shared__ float4 shSu4[16];
    int half = blockIdx.x & 1;
    int n0   = ((blockIdx.x >> 1) & 3) * 32;
    int b    = blockIdx.x >> 3;
    int sb   = half * 64;
    for (int idx = threadIdx.x; idx < 64 * 16; idx += 512)
        *(float4*)&shP[idx * 4] = *(const float4*)&g_P[(b * SS + sb) * DD + idx * 4];
    {
        int idx = threadIdx.x;
        int nr = idx >> 4, sc = idx & 15;
        shC4[idx] = *(const float4*)&g_C[(b * NC + n0 + nr) * SS + sb + sc * 4];
    }
    if (threadIdx.x < 16)
        shSu4[threadIdx.x] = *(const float4*)&g_Su[b * SS + sb + threadIdx.x * 4];
    __syncthreads();
    int d = threadIdx.x & 63, g = threadIdx.x >> 6;   // g 0..7, 4 n each
    const float4* c0 = &shC4[(g * 4 + 0) * 16];
    const float4* c1 = &shC4[(g * 4 + 1) * 16];
    const float4* c2 = &shC4[(g * 4 + 2) * 16];
    const float4* c3 = &shC4[(g * 4 + 3) * 16];
    float a0 = 0, a1 = 0, a2 = 0, a3 = 0, q0 = 0, q1 = 0, q2 = 0, q3 = 0;
    #pragma unroll
    for (int s4 = 0; s4 < 16; s4++) {
        float4 f0 = c0[s4], f1 = c1[s4], f2 = c2[s4], f3 = c3[s4];
        float4 su = shSu4[s4];
        float p0 = shP[(s4 * 4 + 0) * DD + d];
        float p1 = shP[(s4 * 4 + 1) * DD + d];
        float p2 = shP[(s4 * 4 + 2) * DD + d];
        float p3 = shP[(s4 * 4 + 3) * DD + d];
        a0 += f0.x * p0 + f0.y * p1 + f0.z * p2 + f0.w * p3;
        a1 += f1.x * p0 + f1.y * p1 + f1.z * p2 + f1.w * p3;
        a2 += f2.x * p0 + f2.y * p1 + f2.z * p2 + f2.w * p3;
        a3 += f3.x * p0 + f3.y * p1 + f3.z * p2 + f3.w * p3;
        q0 += f0.x * su.x + f0.y * su.y + f0.z * su.z + f0.w * su.w;
        q1 += f1.x * su.x + f1.y * su.y + f1.z * su.z + f1.w * su.w;
        q2 += f2.x * su.x + f2.y * su.y + f2.z * su.z + f2.w * su.w;
        q3 += f3.x * su.x + f3.y * su.y + f3.z * su.z + f3.w * su.w;
    }
    int nb = n0 + g * 4;
    float* T = g_T + half * TOFF;
    T[(b * NC + nb + 0) * DD + d] = a0 + q0 * g_PE1[(nb + 0) * DD + d];
    T[(b * NC + nb + 1) * DD + d] = a1 + q1 * g_PE1[(nb + 1) * DD + d];
    T[(b * NC + nb + 2) * DD + d] = a2 + q2 * g_PE1[(nb + 2) * DD + d];
    T[(b * NC + nb + 3) * DD + d] = a3 + q3 * g_PE1[(nb + 3) * DD + d];
}

// ---------------------------------------------------------------------------
// Output term 3 + squash + fused logit term 3 — 4-wide b register tile.
// grid = 128 (one n per block), 512 threads, ALL 32 b per block.
// Dynamic smem 59 KB (opt-in). PE2 loaded once per n (was twice).
// Phase 1: thread = (d, b-quad): 8 LDS / 16 FMA per s4 (was 6/8).
// Phase 2: thread = (s, 8-b): 9 LDS / 32 FMA per d4 (was 5/16).
// ---------------------------------------------------------------------------
#define OUTB_SMEM (34816 + 16384 + 8192 + 256)
__global__ void __launch_bounds__(512) k_outB(float* __restrict__ dst, int final_,
                                              int it0, const float* __restrict__ mask) {
    extern __shared__ __align__(16) char sm[];
    float*  shPE2 = (float*)sm;                        // 128*68*4 = 34816
    float4* shC4  = (float4*)(sm + 34816);             // 32 b x 32 = 16384
    float*  shV   = (float*)(sm + 34816 + 16384);      // 32*64*4 = 8192
    float4* shRed = (float4*)(sm + 34816 + 16384 + 8192);  // [8][2]
    int n = blockIdx.x;
    float* Vout = final_ ? dst : g_V;
    for (int idx = threadIdx.x; idx < SS * 16; idx += 512) {
        int s = idx >> 4, c = idx & 15;
        *(float4*)&shPE2[s * 68 + c * 4] = *(const float4*)&g_PE2[s * OD + n * DD + c * 4];
    }
    for (int idx = threadIdx.x; idx < 32 * 32; idx += 512) {
        int bl = idx >> 5, sc = idx & 31;
        if (it0) {
            float4 m = *(const float4*)&mask[bl * SS + sc * 4];
            shC4[idx] = make_float4(m.x * (1.0f / 128.0f), m.y * (1.0f / 128.0f),
                                    m.z * (1.0f / 128.0f), m.w * (1.0f / 128.0f));
        } else {
            shC4[idx] = *(const float4*)&g_C[(bl * NC + n) * SS + sc * 4];
        }
    }
    __syncthreads();
    int d = threadIdx.x & 63, g = threadIdx.x >> 6;   // g 0..7, b-quad each
    int lane = threadIdx.x & 31, wig = (threadIdx.x >> 5) & 1;
    int b0 = g * 4;
    const float4* c0 = &shC4[(b0 + 0) * 32];
    const float4* c1 = &shC4[(b0 + 1) * 32];
    const float4* c2 = &shC4[(b0 + 2) * 32];
    const float4* c3 = &shC4[(b0 + 3) * 32];
    float a0 = 0, a1 = 0, a2 = 0, a3 = 0;
    #pragma unroll
    for (int s4 = 0; s4 < 32; s4++) {
        float4 f0 = c0[s4], f1 = c1[s4], f2 = c2[s4], f3 = c3[s4];
        float p0 = shPE2[(s4 * 4 + 0) * 68 + d];
        float p1 = shPE2[(s4 * 4 + 1) * 68 + d];
        float p2 = shPE2[(s4 * 4 + 2) * 68 + d];
        float p3 = shPE2[(s4 * 4 + 3) * 68 + d];
        a0 += f0.x * p0 + f0.y * p1 + f0.z * p2 + f0.w * p3;
        a1 += f1.x * p0 + f1.y * p1 + f1.z * p2 + f1.w * p3;
        a2 += f2.x * p0 + f2.y * p1 + f2.z * p2 + f2.w * p3;
        a3 += f3.x * p0 + f3.y * p1 + f3.z * p2 + f3.w * p3;
    }
    float val0, val1, val2, val3;
    if (it0) {
        float pe = g_PE1[n * DD + d];
        val0 = g_T[(b0 + 0) * DD + d] + g_q[b0 + 0] * pe + a0;
        val1 = g_T[(b0 + 1) * DD + d] + g_q[b0 + 1] * pe + a1;
        val2 = g_T[(b0 + 2) * DD + d] + g_q[b0 + 2] * pe + a2;
        val3 = g_T[(b0 + 3) * DD + d] + g_q[b0 + 3] * pe + a3;
    } else {
        val0 = g_T[((b0 + 0) * NC + n) * DD + d] + g_T[TOFF + ((b0 + 0) * NC + n) * DD + d] + a0;
        val1 = g_T[((b0 + 1) * NC + n) * DD + d] + g_T[TOFF + ((b0 + 1) * NC + n) * DD + d] + a1;
        val2 = g_T[((b0 + 2) * NC + n) * DD + d] + g_T[TOFF + ((b0 + 2) * NC + n) * DD + d] + a2;
        val3 = g_T[((b0 + 3) * NC + n) * DD + d] + g_T[TOFF + ((b0 + 3) * NC + n) * DD + d] + a3;
    }
    float ss0 = val0 * val0, ss1 = val1 * val1, ss2 = val2 * val2, ss3 = val3 * val3;
    #pragma unroll
    for (int off = 16; off; off >>= 1) {
        ss0 += __shfl_xor_sync(0xffffffffu, ss0, off);
        ss1 += __shfl_xor_sync(0xffffffffu, ss1, off);
        ss2 += __shfl_xor_sync(0xffffffffu, ss2, off);
        ss3 += __shfl_xor_sync(0xffffffffu, ss3, off);
    }
    if (lane == 0) shRed[g * 2 + wig] = make_float4(ss0, ss1, ss2, ss3);
    __syncthreads();
    float4 rA = shRed[g * 2], rB = shRed[g * 2 + 1];
    float t0 = rA.x + rB.x, t1 = rA.y + rB.y, t2 = rA.z + rB.z, t3 = rA.w + rB.w;
    float sc0 = t0 / (1.0f + t0) * rsqrtf(t0 + 1e-7f);
    float sc1 = t1 / (1.0f + t1) * rsqrtf(t1 + 1e-7f);
    float sc2 = t2 / (1.0f + t2) * rsqrtf(t2 + 1e-7f);
    float sc3 = t3 / (1.0f + t3) * rsqrtf(t3 + 1e-7f);
    float v0w = sc0 * val0, v1w = sc1 * val1, v2w = sc2 * val2, v3w = sc3 * val3;
    Vout[((b0 + 0) * NC + n) * DD + d] = v0w;
    Vout[((b0 + 1) * NC + n) * DD + d] = v1w;
    Vout[((b0 + 2) * NC + n) * DD + d] = v2w;
    Vout[((b0 + 3) * NC + n) * DD + d] = v3w;
    if (final_) return;
    shV[(b0 + 0) * DD + d] = v0w;
    shV[(b0 + 1) * DD + d] = v1w;
    shV[(b0 + 2) * DD + d] = v2w;
    shV[(b0 + 3) * DD + d] = v3w;
    __syncthreads();
    // Phase 2: Bl[b,n,s] = sum_d V*PE2; thread = (s, 8-b group)
    int s = threadIdx.x & 127, h = threadIdx.x >> 7;  // h 0..3
    const float4* pr = (const float4*)&shPE2[s * 68];
    #pragma unroll
    for (int bq = 0; bq < 2; bq++) {
        int bl = h * 8 + bq * 4;
        const float4* w0 = (const float4*)&shV[(bl + 0) * DD];
        const float4* w1 = (const float4*)&shV[(bl + 1) * DD];
        const float4* w2 = (const float4*)&shV[(bl + 2) * DD];
        const float4* w3 = (const float4*)&shV[(bl + 3) * DD];
        float r0 = 0, r1 = 0, r2 = 0, r3 = 0;
        #pragma unroll
        for (int d4 = 0; d4 < 16; d4++) {
            float4 p = pr[d4];
            float4 x0 = w0[d4], x1 = w1[d4], x2 = w2[d4], x3 = w3[d4];
            r0 += p.x * x0.x + p.y * x0.y + p.z * x0.z + p.w * x0.w;
            r1 += p.x * x1.x + p.y * x1.y + p.z * x1.z + p.w * x1.w;
            r2 += p.x * x2.x + p.y * x2.y + p.z * x2.z + p.w * x2.w;
            r3 += p.x * x3.x + p.y * x3.y + p.z * x3.z + p.w * x3.w;
        }
        g_Bl[((bl + 0) * NC + n) * SS + s] = r0;
        g_Bl[((bl + 1) * NC + n) * SS + s] = r1;
        g_Bl[((bl + 2) * NC + n) * SS + s] = r2;
        g_Bl[((bl + 3) * NC + n) * SS + s] = r3;
    }
}

// ---------------------------------------------------------------------------
// Logit terms 1+2 (accumulate onto term 3). 512 threads; 16 n per block.
// grid = 32 b * 8 ntile = 256.   (identical to R13)
// ---------------------------------------------------------------------------
__global__ void __launch_bounds__(512) k_bA() {
    __shared__ float shP[SS * 68];   // 34.8 KB
    __shared__ float shV[16 * DD];   // 4 KB
    __shared__ float shSu[SS];
    __shared__ float shSc[16];
    int b  = blockIdx.x >> 3;
    int n0 = (blockIdx.x & 7) * 16;
    for (int idx = threadIdx.x; idx < SS * 16; idx += 512) {
        int s = idx >> 4, c = idx & 15;
        *(float4*)&shP[s * 68 + c * 4] = *(const float4*)&g_P[(b * SS + s) * DD + c * 4];
    }
    for (int idx = threadIdx.x; idx < 16 * 16; idx += 512)
        *(float4*)&shV[idx * 4] = *(const float4*)&g_V[(b * NC + n0) * DD + idx * 4];
    if (threadIdx.x < SS) shSu[threadIdx.x] = g_Su[b * SS + threadIdx.x];
    __syncthreads();
    {
        int w = threadIdx.x >> 5, lane = threadIdx.x & 31;
        float t = shV[w * DD + lane]      * g_PE1[(n0 + w) * DD + lane]
                + shV[w * DD + 32 + lane] * g_PE1[(n0 + w) * DD + 32 + lane];
        #pragma unroll
        for (int off = 16; off; off >>= 1)
            t += __shfl_xor_sync(0xffffffffu, t, off);
        if (lane == 0) shSc[w] = t;
    }
    __syncthreads();
    int s = threadIdx.x & 127, h = threadIdx.x >> 7;  // h 0..3, 4 n each
    int nl = h * 4;
    const float4* pr = (const float4*)&shP[s * 68];
    const float4* v0 = (const float4*)&shV[(nl + 0) * DD];
    const float4* v1 = (const float4*)&shV[(nl + 1) * DD];
    const float4* v2 = (const float4*)&shV[(nl + 2) * DD];
    const float4* v3 = (const float4*)&shV[(nl + 3) * DD];
    float a0 = 0, a1 = 0, a2 = 0, a3 = 0;
    #pragma unroll
    for (int d4 = 0; d4 < 16; d4++) {
        float4 p = pr[d4];
        float4 w0 = v0[d4], w1 = v1[d4], w2 = v2[d4], w3 = v3[d4];
        a0 += p.x * w0.x + p.y * w0.y + p.z * w0.z + p.w * w0.w;
        a1 += p.x * w1.x + p.y * w1.y + p.z * w1.z + p.w * w1.w;
        a2 += p.x * w2.x + p.y * w2.y + p.z * w2.z + p.w * w2.w;
        a3 += p.x * w3.x + p.y * w3.y + p.z * w3.z + p.w * w3.w;
    }
    float su = shSu[s];
    g_Bl[(b * NC + n0 + nl + 0) * SS + s] += a0 + su * shSc[nl + 0];
    g_Bl[(b * NC + n0 + nl + 1) * SS + s] += a1 + su * shSc[nl + 1];
    g_Bl[(b * NC + n0 + nl + 2) * SS + s] += a2 + su * shSc[nl + 2];
    g_Bl[(b * NC + n0 + nl + 3) * SS + s] += a3 + su * shSc[nl + 3];
}

// ---------------------------------------------------------------------------
// Softmax over n -> g_C. grid = 128, 256 threads.   (identical to R13)
// ---------------------------------------------------------------------------
__global__ void __launch_bounds__(256) k_softmax(const float* __restrict__ mask) {
    __shared__ float red[2][8][32];
    int b = blockIdx.x >> 2, s0 = (blockIdx.x & 3) * 32;
    int lane = threadIdx.x & 31, w = threadIdx.x >> 5;
    int s = s0 + lane;
    float v[16];
    float mx = -1e30f;
    #pragma unroll
    for (int j = 0; j < 16; j++) {
        v[j] = g_Bl[(b * NC + w * 16 + j) * SS + s];
        mx = fmaxf(mx, v[j]);
    }
    red[0][w][lane] = mx;
    __syncthreads();
    mx = red[0][0][lane];
    #pragma unroll
    for (int w2 = 1; w2 < 8; w2++) mx = fmaxf(mx, red[0][w2][lane]);
    float sum = 0.f;
    #pragma unroll
    for (int j = 0; j < 16; j++) { v[j] = __expf(v[j] - mx); sum += v[j]; }
    red[1][w][lane] = sum;
    __syncthreads();
    sum = red[1][0][lane];
    #pragma unroll
    for (int w2 = 1; w2 < 8; w2++) sum += red[1][w2][lane];
    float scale = mask[b * SS + s] / sum;
    #pragma unroll
    for (int j = 0; j < 16; j++)
        g_C[(b * NC + w * 16 + j) * SS + s] = v[j] * scale;
}

// ---------------------------------------------------------------------------
extern "C" void kernel_launch(void* const* d_in, const int* in_sizes, int n_in,
                              void* d_out, int out_size) {
    const float* u    = (const float*)d_in[0];
    const float* mask = (const float*)d_in[1];
    const float* W    = (const float*)d_in[2];
    float* out = (float*)d_out;

    cudaFuncSetAttribute(k_outB, cudaFuncAttributeMaxDynamicSharedMemorySize, OUTB_SMEM);

    k_init<<<288, 256>>>(u, W);
    k_A0<<<32, 256>>>(mask);

    // iteration 0 (c = mask/128; outA replaced by A0)
    k_outB<<<128, 512, OUTB_SMEM>>>(out, 0, 1, mask);
    k_bA<<<256, 512>>>();
    k_softmax<<<128, 256>>>(mask);
    // iteration 1
    k_outA<<<256, 512>>>();
    k_outB<<<128, 512, OUTB_SMEM>>>(out, 0, 0, mask);
    k_bA<<<256, 512>>>();
    k_softmax<<<128, 256>>>(mask);
    // iteration 2
    k_outA<<<256, 512>>>();
    k_outB<<<128, 512, OUTB_SMEM>>>(out, 1, 0, mask);
}